// round 16
// baseline (speedup 1.0000x reference)
#include <cuda_runtime.h>
#include <cuda_fp16.h>
#include <mma.h>
#include <stdint.h>

using namespace nvcuda;

#define NMAX 100000
#define EMAX 1000000
#define NTILES 128   // >= ceil(NMAX/1024)
#define NPAD (NMAX + 128)

typedef unsigned long long ull;

// ---- static device scratch ----
__device__ __align__(16) ull     g_packed[NMAX];     // count<<40 | deg_fixed(2^-28); zeroed by scan
__device__ __align__(16) uint2   g_se[NMAX];         // (start, end)
__device__ __align__(16) int     g_cursor[NMAX];
__device__ __align__(16) ull     g_status[NTILES];   // lookback: flag(2) | sum<<2
__device__ __align__(16) float   g_dinv[NMAX];
__device__ __align__(16) uint2   g_edge[EMAX];       // (src, ew bits)
__device__ __align__(16) __half  g_Hh[NPAD * 64];    // fp16 h (GEMM A input + residual)
__device__ __align__(16) float   g_S[NPAD * 64];     // hw' = dinv*(h@W), fp32 (gather src)
__device__ __align__(16) __half  g_Wh[3][4096];      // fp16 weights (pre-converted)
__device__ __align__(16) float   g_F[NMAX];          // F' = dinv * (h3.Wf)
__device__ int g_is64;

// ---------------------------------------------------------------------------
__device__ __forceinline__ int edge_at(const void* ei, int idx)
{
    if (g_is64) return (int)((const long long*)ei)[idx];
    return ((const int*)ei)[idx];
}

// ---------------------------------------------------------------------------
// fused: x->fp16 convert + W->fp16 convert + status reset + HISTOGRAM
// ---------------------------------------------------------------------------
__global__ void convert_init_kernel(const float* __restrict__ x, int total4,
                                    const void* __restrict__ ei,
                                    const float* __restrict__ ew,
                                    const float* __restrict__ W0,
                                    const float* __restrict__ W1,
                                    const float* __restrict__ W2,
                                    int E, int n)
{
    __shared__ int s_is64;
    if (threadIdx.x < 32) {
        long long v = ((const long long*)ei)[threadIdx.x];
        unsigned ok = __ballot_sync(0xffffffffu, v >= 0 && v < (long long)n);
        if (threadIdx.x == 0) {
            s_is64 = (ok == 0xffffffffu) ? 1 : 0;
            if (blockIdx.x == 0) g_is64 = s_is64;
        }
    }
    __syncthreads();
    int is64 = s_is64;

    int i = blockIdx.x * blockDim.x + threadIdx.x;
    if (i < NTILES) g_status[i] = 0;
    if (i < 4096) {
        g_Wh[0][i] = __float2half(W0[i]);
        g_Wh[1][i] = __float2half(W1[i]);
        g_Wh[2][i] = __float2half(W2[i]);
    }
    if (i < total4) {
        float4 v = reinterpret_cast<const float4*>(x)[i];
        __half2 lo = __floats2half2_rn(v.x, v.y);
        __half2 hi = __floats2half2_rn(v.z, v.w);
        uint2 o;
        o.x = *reinterpret_cast<unsigned*>(&lo);
        o.y = *reinterpret_cast<unsigned*>(&hi);
        reinterpret_cast<uint2*>(g_Hh)[i] = o;
    }
    if (i < E) {
        int c = is64 ? (int)((const long long*)ei)[E + i] : ((const int*)ei)[E + i];
        if ((unsigned)c < (unsigned)n) {
            ull add = ((ull)1 << 40) + __float2ull_rn(ew[i] * 268435456.0f);
            atomicAdd(&g_packed[c], add);
        }
    }
}

// ---------------------------------------------------------------------------
// single-pass scan (decoupled lookback, tile=1024)
// ---------------------------------------------------------------------------
__global__ void __launch_bounds__(256) scan_kernel(int n)
{
    __shared__ int sd[256];
    __shared__ int s_excl;
    int t = threadIdx.x;
    int b = blockIdx.x;
    int base = b * 1024 + t * 4;

    ull pk[4];
    int cnt[4];
#pragma unroll
    for (int q = 0; q < 4; q++) {
        pk[q] = (base + q < n) ? g_packed[base + q] : 0ull;
        cnt[q] = (int)(pk[q] >> 40);
    }
    int tsum = cnt[0] + cnt[1] + cnt[2] + cnt[3];
    sd[t] = tsum;
    __syncthreads();
    int x = tsum;
    for (int off = 1; off < 256; off <<= 1) {
        int y = (t >= off) ? sd[t - off] : 0;
        __syncthreads();
        x += y;
        sd[t] = x;
        __syncthreads();
    }
    int thr_excl = x - tsum;
    int agg = sd[255];
    __syncthreads();

    if (t == 0) {
        ull st = b == 0 ? (2ull | ((ull)agg << 2)) : (1ull | ((ull)agg << 2));
        atomicExch(&g_status[b], st);
    }

    if (t < 32) {
        int excl = 0;
        if (b > 0) {
            int j = b - 1;
            for (;;) {
                int idx = j - (int)t;
                ull st = 0;
                if (idx >= 0) {
                    do { st = atomicAdd(&g_status[idx], 0ull); } while ((st & 3ull) == 0ull);
                }
                unsigned pmask = __ballot_sync(0xffffffffu, idx >= 0 && (st & 3ull) == 2ull);
                int val = (int)(st >> 2);
                if (pmask) {
                    int lead = __ffs(pmask) - 1;
                    int contrib = (t <= lead && idx >= 0) ? val : 0;
                    for (int o = 16; o; o >>= 1) contrib += __shfl_xor_sync(0xffffffffu, contrib, o);
                    excl += contrib;
                    break;
                } else {
                    int contrib = (idx >= 0) ? val : 0;
                    for (int o = 16; o; o >>= 1) contrib += __shfl_xor_sync(0xffffffffu, contrib, o);
                    excl += contrib;
                    j -= 32;
                }
            }
            if (t == 0) atomicExch(&g_status[b], 2ull | ((ull)(excl + agg) << 2));
        }
        if (t == 0) s_excl = excl;
    }
    __syncthreads();

    int run = s_excl + thr_excl;
#pragma unroll
    for (int q = 0; q < 4; q++) {
        int i = base + q;
        if (i < n) {
            g_se[i] = make_uint2((unsigned)run, (unsigned)(run + cnt[q]));
            g_cursor[i] = run;
            float deg = 1.0f + (float)(pk[q] & (((ull)1 << 40) - 1)) * (1.0f / 268435456.0f);
            g_dinv[i] = rsqrtf(deg);
            g_packed[i] = 0;          // recycle for next replay
            run += cnt[q];
        }
    }
}

// ---------------------------------------------------------------------------
// GEMM body (256 thr, 64 rows): g_S[row] = dinv[row] * (g_Hh[row] @ Wh[widx])
// fp32 output, no pack.
// ---------------------------------------------------------------------------
__device__ __forceinline__ void gemm_block_body(int gb, int widx, int n)
{
    __shared__ __align__(16) __half sW[64 * 72];
    __shared__ __align__(16) char sbuf[64 * 68 * 4];   // union: sA / sC
    __half* sA = reinterpret_cast<__half*>(sbuf);
    float*  sC = reinterpret_cast<float*>(sbuf);

    int t = threadIdx.x;
    {
        const uint4* wsrc = reinterpret_cast<const uint4*>(g_Wh[widx]);
        for (int i = t; i < 512; i += 256) {
            int r = i >> 3, j = i & 7;
            *reinterpret_cast<uint4*>(sW + r * 72 + j * 8) = wsrc[i];
        }
    }
    int row0 = gb * 64;
    {
        int row = t >> 2, j4 = t & 3;
        const uint4* src = reinterpret_cast<const uint4*>(
            g_Hh + (size_t)(row0 + row) * 64 + j4 * 16);
        uint4* dst = reinterpret_cast<uint4*>(sA + row * 72 + j4 * 16);
        dst[0] = src[0];
        dst[1] = src[1];
    }
    __syncthreads();

    int warp = t >> 5;
    wmma::fragment<wmma::accumulator, 16, 16, 16, float> c[4];
    if (warp < 4) {
#pragma unroll
        for (int j = 0; j < 4; j++) wmma::fill_fragment(c[j], 0.0f);
#pragma unroll
        for (int k = 0; k < 4; k++) {
            wmma::fragment<wmma::matrix_a, 16, 16, 16, __half, wmma::row_major> a;
            wmma::load_matrix_sync(a, sA + (warp * 16) * 72 + k * 16, 72);
#pragma unroll
            for (int j = 0; j < 4; j++) {
                wmma::fragment<wmma::matrix_b, 16, 16, 16, __half, wmma::row_major> b;
                wmma::load_matrix_sync(b, sW + (k * 16) * 72 + j * 16, 72);
                wmma::mma_sync(c[j], a, b, c[j]);
            }
        }
    }
    __syncthreads();   // sA reads done before sC overwrites union
    if (warp < 4) {
#pragma unroll
        for (int j = 0; j < 4; j++)
            wmma::store_matrix_sync(sC + (warp * 16) * 68 + j * 16, c[j], 68,
                                    wmma::mem_row_major);
    }
    __syncthreads();

    {
        int row = t >> 2, q = t & 3;
        int gr = row0 + row;
        float dv = (gr < n) ? g_dinv[gr] : 0.f;
        const float4* src = reinterpret_cast<const float4*>(sC + row * 68 + q * 16);
        float4* dst = reinterpret_cast<float4*>(g_S + (size_t)gr * 64 + q * 16);
#pragma unroll
        for (int h = 0; h < 4; h++) {
            float4 p = src[h];
            dst[h] = make_float4(p.x * dv, p.y * dv, p.z * dv, p.w * dv);
        }
    }
}

__global__ void __launch_bounds__(256) gemm_kernel(int widx, int n)
{
    gemm_block_body(blockIdx.x, widx, n);
}

// ---------------------------------------------------------------------------
// fused GEMM(layer1) + CSR build: blocks [0,nbGm) gemm, [nbGm,..) build
// ---------------------------------------------------------------------------
__global__ void __launch_bounds__(256) gemm_build_kernel(const void* __restrict__ ei,
                                                         const float* __restrict__ ew,
                                                         int E, int n, int nbGm)
{
    if ((int)blockIdx.x < nbGm) {
        gemm_block_body(blockIdx.x, 0, n);
        return;
    }
    int e = (blockIdx.x - nbGm) * 256 + threadIdx.x;
    if (e < E) {
        int r = edge_at(ei, e);
        int c = edge_at(ei, E + e);
        if ((unsigned)r < (unsigned)n && (unsigned)c < (unsigned)n) {
            int p = atomicAdd(&g_cursor[c], 1);
            if ((unsigned)p < (unsigned)EMAX)
                g_edge[p] = make_uint2((unsigned)r, __float_as_uint(ew[e]));
        }
    }
}

// ---------------------------------------------------------------------------
// gather: hw'[i] + sum_e ew_e * hw'[src_e]  (fp32 payload; caller scales by dinv)
// ---------------------------------------------------------------------------
__device__ __forceinline__ float2 gather_node(int i, int lane)
{
    const float2* hw2 = reinterpret_cast<const float2*>(g_S);
    float2 v = hw2[(size_t)i * 32 + lane];   // self, coeff 1
    float ax = v.x, ay = v.y;
    float a1x = 0.f, a1y = 0.f, a2x = 0.f, a2y = 0.f, a3x = 0.f, a3y = 0.f;

    uint2 se = g_se[i];
    int e = (int)se.x, end = (int)se.y;
    for (; e + 4 <= end; e += 4) {
        uint2 e0 = g_edge[e], e1 = g_edge[e + 1], e2 = g_edge[e + 2], e3 = g_edge[e + 3];
        float2 v0 = hw2[(size_t)e0.x * 32 + lane];
        float2 v1 = hw2[(size_t)e1.x * 32 + lane];
        float2 v2 = hw2[(size_t)e2.x * 32 + lane];
        float2 v3 = hw2[(size_t)e3.x * 32 + lane];
        float n0 = __uint_as_float(e0.y), n1 = __uint_as_float(e1.y);
        float n2 = __uint_as_float(e2.y), n3 = __uint_as_float(e3.y);
        ax  += n0 * v0.x; ay  += n0 * v0.y;
        a1x += n1 * v1.x; a1y += n1 * v1.y;
        a2x += n2 * v2.x; a2y += n2 * v2.y;
        a3x += n3 * v3.x; a3y += n3 * v3.y;
    }
    for (; e < end; e++) {
        uint2 e0 = g_edge[e];
        float2 v0 = hw2[(size_t)e0.x * 32 + lane];
        float n0 = __uint_as_float(e0.y);
        ax += n0 * v0.x; ay += n0 * v0.y;
    }
    ax += a1x + a2x + a3x;
    ay += a1y + a2y + a3y;
    return make_float2(ax, ay);
}

// layers 1,2: h' = relu(dinv*gather + bias (+resid fp16)) -> g_Hh (fp16)
__global__ void __launch_bounds__(256) agg_kernel(const float* __restrict__ bias,
                                                  int use_resid, int n)
{
    int wid = (blockIdx.x * blockDim.x + threadIdx.x) >> 5;
    int lane = threadIdx.x & 31;
    if (wid >= n) return;

    float di = g_dinv[wid];
    float2 a = gather_node(wid, lane);
    float2 bb = reinterpret_cast<const float2*>(bias)[lane];
    a.x = di * a.x + bb.x;
    a.y = di * a.y + bb.y;
    __half2* hh = reinterpret_cast<__half2*>(g_Hh) + (size_t)wid * 32 + lane;
    if (use_resid) {
        float2 r = __half22float2(*hh);   // previous layer h (fp16)
        a.x += r.x; a.y += r.y;
    }
    a.x = fmaxf(a.x, 0.f); a.y = fmaxf(a.y, 0.f);
    *hh = __floats2half2_rn(a.x, a.y);
}

// layer 3 + GEMV: F'[i] = dinv[i] * ( relu(dinv*gather + b2 + resid) . Wf )
__global__ void __launch_bounds__(256) agg3_kernel(const float* __restrict__ bias,
                                                   const float* __restrict__ Wf, int n)
{
    int wid = (blockIdx.x * blockDim.x + threadIdx.x) >> 5;
    int lane = threadIdx.x & 31;
    if (wid >= n) return;

    float di = g_dinv[wid];
    float2 a = gather_node(wid, lane);
    float2 bb = reinterpret_cast<const float2*>(bias)[lane];
    a.x = di * a.x + bb.x;
    a.y = di * a.y + bb.y;
    float2 r = __half22float2(
        reinterpret_cast<const __half2*>(g_Hh)[(size_t)wid * 32 + lane]);   // h2
    a.x += r.x; a.y += r.y;
    a.x = fmaxf(a.x, 0.f); a.y = fmaxf(a.y, 0.f);

    float2 wf = reinterpret_cast<const float2*>(Wf)[lane];
    float p = a.x * wf.x + a.y * wf.y;
#pragma unroll
    for (int o = 16; o; o >>= 1) p += __shfl_xor_sync(0xffffffffu, p, o);
    if (lane == 0) g_F[wid] = di * p;
}

// ---------------------------------------------------------------------------
// final: out[i] = dinv[i] * ( F'[i] + sum_e ew_e * F'[src] ) + bf
// ---------------------------------------------------------------------------
__global__ void agg_final_kernel(const float* __restrict__ bf,
                                 float* __restrict__ out, int n)
{
    int i = blockIdx.x * blockDim.x + threadIdx.x;
    if (i >= n) return;
    float acc = g_F[i];
    float a1 = 0.f, a2 = 0.f, a3 = 0.f;
    uint2 se = g_se[i];
    int e = (int)se.x, end = (int)se.y;
    for (; e + 4 <= end; e += 4) {
        uint2 e0 = g_edge[e], e1 = g_edge[e + 1], e2 = g_edge[e + 2], e3 = g_edge[e + 3];
        acc += __uint_as_float(e0.y) * g_F[e0.x];
        a1  += __uint_as_float(e1.y) * g_F[e1.x];
        a2  += __uint_as_float(e2.y) * g_F[e2.x];
        a3  += __uint_as_float(e3.y) * g_F[e3.x];
    }
    for (; e < end; e++) {
        uint2 e0 = g_edge[e];
        acc += __uint_as_float(e0.y) * g_F[e0.x];
    }
    out[i] = g_dinv[i] * (acc + a1 + a2 + a3) + bf[0];
}

// ---------------------------------------------------------------------------
// Launch
// ---------------------------------------------------------------------------
extern "C" void kernel_launch(void* const* d_in, const int* in_sizes, int n_in,
                              void* d_out, int out_size)
{
    const float* x    = (const float*)d_in[0];
    const void*  ei   = d_in[1];
    const float* ew   = (const float*)d_in[2];
    const float* W_in = (const float*)d_in[4];
    const float* b_in = (const float*)d_in[5];
    const float* W1   = (const float*)d_in[6];
    const float* b1   = (const float*)d_in[7];
    const float* W2   = (const float*)d_in[8];
    const float* b2   = (const float*)d_in[9];
    const float* Wf   = (const float*)d_in[10];
    const float* bf   = (const float*)d_in[11];
    float* out = (float*)d_out;

    int n = in_sizes[0] / 64;
    int E = in_sizes[2];

    int nbN  = (n + 255) / 256;
    int nbE  = (E + 255) / 256;
    int nbSc = (n + 1023) / 1024;       // <= NTILES
    int total4 = n * 16;
    int nbCv = ((total4 > E ? total4 : E) + 255) / 256;
    int nbAg = (n + 7) / 8;             // warp per node
    int nbGm = (n + 63) / 64;           // 64 rows per gemm block

    convert_init_kernel<<<nbCv, 256>>>(x, total4, ei, ew,
                                       W_in, W1, W2, E, n);       // 0
    scan_kernel<<<nbSc, 256>>>(n);                                // 1
    gemm_build_kernel<<<nbGm + nbE, 256>>>(ei, ew, E, n, nbGm);   // 2 (gemm1 || build)
    agg_kernel<<<nbAg, 256>>>(b_in, 0, n);                        // 3 (profiled)
    gemm_kernel<<<nbGm, 256>>>(1, n);                             // 4
    agg_kernel<<<nbAg, 256>>>(b1, 1, n);                          // 5
    gemm_kernel<<<nbGm, 256>>>(2, n);                             // 6
    agg3_kernel<<<nbAg, 256>>>(b2, Wf, n);                        // 7
    agg_final_kernel<<<nbN, 256>>>(bf, out, n);                   // 8
}

// round 17
// speedup vs baseline: 1.1611x; 1.1611x over previous
#include <cuda_runtime.h>
#include <cuda_fp16.h>
#include <mma.h>
#include <stdint.h>

using namespace nvcuda;

#define NMAX 100000
#define EMAX 1000000
#define NTILES 128   // >= ceil(NMAX/1024)
#define NPAD (NMAX + 128)

typedef unsigned long long ull;

// ---- static device scratch ----
__device__ __align__(16) ull     g_packed[NMAX];     // count<<40 | deg_fixed(2^-28); zeroed by scan
__device__ __align__(16) uint2   g_se[NMAX];         // (start, end)
__device__ __align__(16) int     g_cursor[NMAX];
__device__ __align__(16) ull     g_status[NTILES];   // lookback: flag(2) | sum<<2
__device__ __align__(16) float   g_dinv[NMAX];
__device__ __align__(16) uint2   g_edge[EMAX];       // (src, ew bits)
__device__ __align__(16) __half  g_Hh[NPAD * 64];    // fp16 h (GEMM A input + residual)
__device__ __align__(16) __half2 g_Shw[NPAD * 32];   // hw' = dinv*(h@W), fp16
__device__ __align__(16) __half  g_Wh[3][4096];      // fp16 weights (pre-converted)
__device__ __align__(16) float   g_F[NMAX];          // F' = dinv * (h3.Wf)
__device__ int g_is64;

// ---------------------------------------------------------------------------
__device__ __forceinline__ int edge_at(const void* ei, int idx)
{
    if (g_is64) return (int)((const long long*)ei)[idx];
    return ((const int*)ei)[idx];
}

// ---------------------------------------------------------------------------
// fused: x->fp16 convert + W->fp16 convert + status reset + HISTOGRAM
// ---------------------------------------------------------------------------
__global__ void convert_init_kernel(const float* __restrict__ x, int total4,
                                    const void* __restrict__ ei,
                                    const float* __restrict__ ew,
                                    const float* __restrict__ W0,
                                    const float* __restrict__ W1,
                                    const float* __restrict__ W2,
                                    int E, int n)
{
    __shared__ int s_is64;
    if (threadIdx.x < 32) {
        long long v = ((const long long*)ei)[threadIdx.x];
        unsigned ok = __ballot_sync(0xffffffffu, v >= 0 && v < (long long)n);
        if (threadIdx.x == 0) {
            s_is64 = (ok == 0xffffffffu) ? 1 : 0;
            if (blockIdx.x == 0) g_is64 = s_is64;
        }
    }
    __syncthreads();
    int is64 = s_is64;

    int i = blockIdx.x * blockDim.x + threadIdx.x;
    if (i < NTILES) g_status[i] = 0;
    if (i < 4096) {
        g_Wh[0][i] = __float2half(W0[i]);
        g_Wh[1][i] = __float2half(W1[i]);
        g_Wh[2][i] = __float2half(W2[i]);
    }
    if (i < total4) {
        float4 v = reinterpret_cast<const float4*>(x)[i];
        __half2 lo = __floats2half2_rn(v.x, v.y);
        __half2 hi = __floats2half2_rn(v.z, v.w);
        uint2 o;
        o.x = *reinterpret_cast<unsigned*>(&lo);
        o.y = *reinterpret_cast<unsigned*>(&hi);
        reinterpret_cast<uint2*>(g_Hh)[i] = o;
    }
    if (i < E) {
        int c = is64 ? (int)((const long long*)ei)[E + i] : ((const int*)ei)[E + i];
        if ((unsigned)c < (unsigned)n) {
            ull add = ((ull)1 << 40) + __float2ull_rn(ew[i] * 268435456.0f);
            atomicAdd(&g_packed[c], add);
        }
    }
}

// ---------------------------------------------------------------------------
// single-pass scan (decoupled lookback, tile=1024)
// ---------------------------------------------------------------------------
__global__ void __launch_bounds__(256) scan_kernel(int n)
{
    __shared__ int sd[256];
    __shared__ int s_excl;
    int t = threadIdx.x;
    int b = blockIdx.x;
    int base = b * 1024 + t * 4;

    ull pk[4];
    int cnt[4];
#pragma unroll
    for (int q = 0; q < 4; q++) {
        pk[q] = (base + q < n) ? g_packed[base + q] : 0ull;
        cnt[q] = (int)(pk[q] >> 40);
    }
    int tsum = cnt[0] + cnt[1] + cnt[2] + cnt[3];
    sd[t] = tsum;
    __syncthreads();
    int x = tsum;
    for (int off = 1; off < 256; off <<= 1) {
        int y = (t >= off) ? sd[t - off] : 0;
        __syncthreads();
        x += y;
        sd[t] = x;
        __syncthreads();
    }
    int thr_excl = x - tsum;
    int agg = sd[255];
    __syncthreads();

    if (t == 0) {
        ull st = b == 0 ? (2ull | ((ull)agg << 2)) : (1ull | ((ull)agg << 2));
        atomicExch(&g_status[b], st);
    }

    if (t < 32) {
        int excl = 0;
        if (b > 0) {
            int j = b - 1;
            for (;;) {
                int idx = j - (int)t;
                ull st = 0;
                if (idx >= 0) {
                    do { st = atomicAdd(&g_status[idx], 0ull); } while ((st & 3ull) == 0ull);
                }
                unsigned pmask = __ballot_sync(0xffffffffu, idx >= 0 && (st & 3ull) == 2ull);
                int val = (int)(st >> 2);
                if (pmask) {
                    int lead = __ffs(pmask) - 1;
                    int contrib = (t <= lead && idx >= 0) ? val : 0;
                    for (int o = 16; o; o >>= 1) contrib += __shfl_xor_sync(0xffffffffu, contrib, o);
                    excl += contrib;
                    break;
                } else {
                    int contrib = (idx >= 0) ? val : 0;
                    for (int o = 16; o; o >>= 1) contrib += __shfl_xor_sync(0xffffffffu, contrib, o);
                    excl += contrib;
                    j -= 32;
                }
            }
            if (t == 0) atomicExch(&g_status[b], 2ull | ((ull)(excl + agg) << 2));
        }
        if (t == 0) s_excl = excl;
    }
    __syncthreads();

    int run = s_excl + thr_excl;
#pragma unroll
    for (int q = 0; q < 4; q++) {
        int i = base + q;
        if (i < n) {
            g_se[i] = make_uint2((unsigned)run, (unsigned)(run + cnt[q]));
            g_cursor[i] = run;
            float deg = 1.0f + (float)(pk[q] & (((ull)1 << 40) - 1)) * (1.0f / 268435456.0f);
            g_dinv[i] = rsqrtf(deg);
            g_packed[i] = 0;          // recycle for next replay
            run += cnt[q];
        }
    }
}

// ---------------------------------------------------------------------------
// GEMM body (256 thr, 64 rows): g_Shw[row] = dinv[row] * (g_Hh[row] @ Wh[widx])
// ---------------------------------------------------------------------------
__device__ __forceinline__ void gemm_block_body(int gb, int widx, int n)
{
    __shared__ __align__(16) __half sW[64 * 72];
    __shared__ __align__(16) char sbuf[64 * 68 * 4];   // union: sA / sC
    __half* sA = reinterpret_cast<__half*>(sbuf);
    float*  sC = reinterpret_cast<float*>(sbuf);

    int t = threadIdx.x;
    {
        const uint4* wsrc = reinterpret_cast<const uint4*>(g_Wh[widx]);
        for (int i = t; i < 512; i += 256) {
            int r = i >> 3, j = i & 7;
            *reinterpret_cast<uint4*>(sW + r * 72 + j * 8) = wsrc[i];
        }
    }
    int row0 = gb * 64;
    {
        int row = t >> 2, j4 = t & 3;
        const uint4* src = reinterpret_cast<const uint4*>(
            g_Hh + (size_t)(row0 + row) * 64 + j4 * 16);
        uint4* dst = reinterpret_cast<uint4*>(sA + row * 72 + j4 * 16);
        dst[0] = src[0];
        dst[1] = src[1];
    }
    __syncthreads();

    int warp = t >> 5;
    wmma::fragment<wmma::accumulator, 16, 16, 16, float> c[4];
    if (warp < 4) {
#pragma unroll
        for (int j = 0; j < 4; j++) wmma::fill_fragment(c[j], 0.0f);
#pragma unroll
        for (int k = 0; k < 4; k++) {
            wmma::fragment<wmma::matrix_a, 16, 16, 16, __half, wmma::row_major> a;
            wmma::load_matrix_sync(a, sA + (warp * 16) * 72 + k * 16, 72);
#pragma unroll
            for (int j = 0; j < 4; j++) {
                wmma::fragment<wmma::matrix_b, 16, 16, 16, __half, wmma::row_major> b;
                wmma::load_matrix_sync(b, sW + (k * 16) * 72 + j * 16, 72);
                wmma::mma_sync(c[j], a, b, c[j]);
            }
        }
    }
    __syncthreads();   // sA reads done before sC overwrites union
    if (warp < 4) {
#pragma unroll
        for (int j = 0; j < 4; j++)
            wmma::store_matrix_sync(sC + (warp * 16) * 68 + j * 16, c[j], 68,
                                    wmma::mem_row_major);
    }
    __syncthreads();

    {
        int row = t >> 2, q = t & 3;
        int gr = row0 + row;
        float dv = (gr < n) ? g_dinv[gr] : 0.f;
        const float2* src = reinterpret_cast<const float2*>(sC + row * 68 + q * 16);
        uint4* dst = reinterpret_cast<uint4*>(g_Shw + (size_t)gr * 32 + q * 8);
#pragma unroll
        for (int h = 0; h < 2; h++) {
            float2 p0 = src[4 * h + 0], p1 = src[4 * h + 1];
            float2 p2 = src[4 * h + 2], p3 = src[4 * h + 3];
            __half2 h0 = __floats2half2_rn(p0.x * dv, p0.y * dv);
            __half2 h1 = __floats2half2_rn(p1.x * dv, p1.y * dv);
            __half2 h2 = __floats2half2_rn(p2.x * dv, p2.y * dv);
            __half2 h3 = __floats2half2_rn(p3.x * dv, p3.y * dv);
            dst[h] = make_uint4(*reinterpret_cast<unsigned*>(&h0),
                                *reinterpret_cast<unsigned*>(&h1),
                                *reinterpret_cast<unsigned*>(&h2),
                                *reinterpret_cast<unsigned*>(&h3));
        }
    }
}

__global__ void __launch_bounds__(256) gemm_kernel(int widx, int n)
{
    gemm_block_body(blockIdx.x, widx, n);
}

// ---------------------------------------------------------------------------
// fused GEMM(layer1) + CSR build: blocks [0,nbGm) gemm, [nbGm,..) build
// ---------------------------------------------------------------------------
__global__ void __launch_bounds__(256) gemm_build_kernel(const void* __restrict__ ei,
                                                         const float* __restrict__ ew,
                                                         int E, int n, int nbGm)
{
    if ((int)blockIdx.x < nbGm) {
        gemm_block_body(blockIdx.x, 0, n);
        return;
    }
    int e = (blockIdx.x - nbGm) * 256 + threadIdx.x;
    if (e < E) {
        int r = edge_at(ei, e);
        int c = edge_at(ei, E + e);
        if ((unsigned)r < (unsigned)n && (unsigned)c < (unsigned)n) {
            int p = atomicAdd(&g_cursor[c], 1);
            if ((unsigned)p < (unsigned)EMAX)
                g_edge[p] = make_uint2((unsigned)r, __float_as_uint(ew[e]));
        }
    }
}

// ---------------------------------------------------------------------------
// gather v2: fp16 payload, latency-optimized.
// - leading element to align e to even, then ulonglong2 loads (2 edges/LDG.128)
// - unroll-8 main loop: all 8 edge loads + 8 gathers issued per epoch (MLP 8)
// ---------------------------------------------------------------------------
__device__ __forceinline__ float2 gather_node(int i, int lane)
{
    float2 v = __half22float2(g_Shw[(size_t)i * 32 + lane]);   // self, coeff 1
    float ax = v.x, ay = v.y;
    float a1x = 0.f, a1y = 0.f, a2x = 0.f, a2y = 0.f, a3x = 0.f, a3y = 0.f;

    uint2 se = g_se[i];
    int e = (int)se.x, end = (int)se.y;

    // align to even index for 16B paired loads
    if ((e & 1) && e < end) {
        uint2 e0 = g_edge[e];
        float2 v0 = __half22float2(g_Shw[(size_t)e0.x * 32 + lane]);
        float n0 = __uint_as_float(e0.y);
        ax += n0 * v0.x; ay += n0 * v0.y;
        e++;
    }

    const ulonglong2* ep = reinterpret_cast<const ulonglong2*>(g_edge);

    // unroll-8: 4 paired loads -> 8 gathers -> 16 FMA chains
    for (; e + 8 <= end; e += 8) {
        ulonglong2 p0 = ep[(e >> 1) + 0];
        ulonglong2 p1 = ep[(e >> 1) + 1];
        ulonglong2 p2 = ep[(e >> 1) + 2];
        ulonglong2 p3 = ep[(e >> 1) + 3];
        unsigned s0 = (unsigned)p0.x, s1 = (unsigned)p0.y;
        unsigned s2 = (unsigned)p1.x, s3 = (unsigned)p1.y;
        unsigned s4 = (unsigned)p2.x, s5 = (unsigned)p2.y;
        unsigned s6 = (unsigned)p3.x, s7 = (unsigned)p3.y;
        float2 v0 = __half22float2(g_Shw[(size_t)s0 * 32 + lane]);
        float2 v1 = __half22float2(g_Shw[(size_t)s1 * 32 + lane]);
        float2 v2 = __half22float2(g_Shw[(size_t)s2 * 32 + lane]);
        float2 v3 = __half22float2(g_Shw[(size_t)s3 * 32 + lane]);
        float2 v4 = __half22float2(g_Shw[(size_t)s4 * 32 + lane]);
        float2 v5 = __half22float2(g_Shw[(size_t)s5 * 32 + lane]);
        float2 v6 = __half22float2(g_Shw[(size_t)s6 * 32 + lane]);
        float2 v7 = __half22float2(g_Shw[(size_t)s7 * 32 + lane]);
        float n0 = __uint_as_float((unsigned)(p0.x >> 32));
        float n1 = __uint_as_float((unsigned)(p0.y >> 32));
        float n2 = __uint_as_float((unsigned)(p1.x >> 32));
        float n3 = __uint_as_float((unsigned)(p1.y >> 32));
        float n4 = __uint_as_float((unsigned)(p2.x >> 32));
        float n5 = __uint_as_float((unsigned)(p2.y >> 32));
        float n6 = __uint_as_float((unsigned)(p3.x >> 32));
        float n7 = __uint_as_float((unsigned)(p3.y >> 32));
        ax  += n0 * v0.x; ay  += n0 * v0.y;
        a1x += n1 * v1.x; a1y += n1 * v1.y;
        a2x += n2 * v2.x; a2y += n2 * v2.y;
        a3x += n3 * v3.x; a3y += n3 * v3.y;
        ax  += n4 * v4.x; ay  += n4 * v4.y;
        a1x += n5 * v5.x; a1y += n5 * v5.y;
        a2x += n6 * v6.x; a2y += n6 * v6.y;
        a3x += n7 * v7.x; a3y += n7 * v7.y;
    }
    // paired remainder
    for (; e + 2 <= end; e += 2) {
        ulonglong2 p0 = ep[e >> 1];
        unsigned s0 = (unsigned)p0.x, s1 = (unsigned)p0.y;
        float2 v0 = __half22float2(g_Shw[(size_t)s0 * 32 + lane]);
        float2 v1 = __half22float2(g_Shw[(size_t)s1 * 32 + lane]);
        float n0 = __uint_as_float((unsigned)(p0.x >> 32));
        float n1 = __uint_as_float((unsigned)(p0.y >> 32));
        ax  += n0 * v0.x; ay  += n0 * v0.y;
        a1x += n1 * v1.x; a1y += n1 * v1.y;
    }
    if (e < end) {
        uint2 e0 = g_edge[e];
        float2 v0 = __half22float2(g_Shw[(size_t)e0.x * 32 + lane]);
        float n0 = __uint_as_float(e0.y);
        ax += n0 * v0.x; ay += n0 * v0.y;
    }
    ax += a1x + a2x + a3x;
    ay += a1y + a2y + a3y;
    return make_float2(ax, ay);
}

// layers 1,2: h' = relu(dinv*gather + bias (+resid fp16)) -> g_Hh (fp16 only)
__global__ void __launch_bounds__(256, 8) agg_kernel(const float* __restrict__ bias,
                                                     int use_resid, int n)
{
    int wid = (blockIdx.x * blockDim.x + threadIdx.x) >> 5;
    int lane = threadIdx.x & 31;
    if (wid >= n) return;

    float di = g_dinv[wid];
    float2 a = gather_node(wid, lane);
    float2 bb = reinterpret_cast<const float2*>(bias)[lane];
    a.x = di * a.x + bb.x;
    a.y = di * a.y + bb.y;
    __half2* hh = reinterpret_cast<__half2*>(g_Hh) + (size_t)wid * 32 + lane;
    if (use_resid) {
        float2 r = __half22float2(*hh);   // previous layer h (fp16)
        a.x += r.x; a.y += r.y;
    }
    a.x = fmaxf(a.x, 0.f); a.y = fmaxf(a.y, 0.f);
    *hh = __floats2half2_rn(a.x, a.y);
}

// layer 3 + GEMV: F'[i] = dinv[i] * ( relu(dinv*gather + b2 + resid) . Wf )
__global__ void __launch_bounds__(256, 8) agg3_kernel(const float* __restrict__ bias,
                                                      const float* __restrict__ Wf, int n)
{
    int wid = (blockIdx.x * blockDim.x + threadIdx.x) >> 5;
    int lane = threadIdx.x & 31;
    if (wid >= n) return;

    float di = g_dinv[wid];
    float2 a = gather_node(wid, lane);
    float2 bb = reinterpret_cast<const float2*>(bias)[lane];
    a.x = di * a.x + bb.x;
    a.y = di * a.y + bb.y;
    float2 r = __half22float2(
        reinterpret_cast<const __half2*>(g_Hh)[(size_t)wid * 32 + lane]);   // h2
    a.x += r.x; a.y += r.y;
    a.x = fmaxf(a.x, 0.f); a.y = fmaxf(a.y, 0.f);

    float2 wf = reinterpret_cast<const float2*>(Wf)[lane];
    float p = a.x * wf.x + a.y * wf.y;
#pragma unroll
    for (int o = 16; o; o >>= 1) p += __shfl_xor_sync(0xffffffffu, p, o);
    if (lane == 0) g_F[wid] = di * p;
}

// ---------------------------------------------------------------------------
// final: out[i] = dinv[i] * ( F'[i] + sum_e ew_e * F'[src] ) + bf
// ---------------------------------------------------------------------------
__global__ void agg_final_kernel(const float* __restrict__ bf,
                                 float* __restrict__ out, int n)
{
    int i = blockIdx.x * blockDim.x + threadIdx.x;
    if (i >= n) return;
    float acc = g_F[i];
    float a1 = 0.f, a2 = 0.f, a3 = 0.f;
    uint2 se = g_se[i];
    int e = (int)se.x, end = (int)se.y;
    for (; e + 4 <= end; e += 4) {
        uint2 e0 = g_edge[e], e1 = g_edge[e + 1], e2 = g_edge[e + 2], e3 = g_edge[e + 3];
        acc += __uint_as_float(e0.y) * g_F[e0.x];
        a1  += __uint_as_float(e1.y) * g_F[e1.x];
        a2  += __uint_as_float(e2.y) * g_F[e2.x];
        a3  += __uint_as_float(e3.y) * g_F[e3.x];
    }
    for (; e < end; e++) {
        uint2 e0 = g_edge[e];
        acc += __uint_as_float(e0.y) * g_F[e0.x];
    }
    out[i] = g_dinv[i] * (acc + a1 + a2 + a3) + bf[0];
}

// ---------------------------------------------------------------------------
// Launch
// ---------------------------------------------------------------------------
extern "C" void kernel_launch(void* const* d_in, const int* in_sizes, int n_in,
                              void* d_out, int out_size)
{
    const float* x    = (const float*)d_in[0];
    const void*  ei   = d_in[1];
    const float* ew   = (const float*)d_in[2];
    const float* W_in = (const float*)d_in[4];
    const float* b_in = (const float*)d_in[5];
    const float* W1   = (const float*)d_in[6];
    const float* b1   = (const float*)d_in[7];
    const float* W2   = (const float*)d_in[8];
    const float* b2   = (const float*)d_in[9];
    const float* Wf   = (const float*)d_in[10];
    const float* bf   = (const float*)d_in[11];
    float* out = (float*)d_out;

    int n = in_sizes[0] / 64;
    int E = in_sizes[2];

    int nbN  = (n + 255) / 256;
    int nbE  = (E + 255) / 256;
    int nbSc = (n + 1023) / 1024;       // <= NTILES
    int total4 = n * 16;
    int nbCv = ((total4 > E ? total4 : E) + 255) / 256;
    int nbAg = (n + 7) / 8;             // warp per node
    int nbGm = (n + 63) / 64;           // 64 rows per gemm block

    convert_init_kernel<<<nbCv, 256>>>(x, total4, ei, ew,
                                       W_in, W1, W2, E, n);       // 0
    scan_kernel<<<nbSc, 256>>>(n);                                // 1
    gemm_build_kernel<<<nbGm + nbE, 256>>>(ei, ew, E, n, nbGm);   // 2 (gemm1 || build)
    agg_kernel<<<nbAg, 256>>>(b_in, 0, n);                        // 3 (profiled)
    gemm_kernel<<<nbGm, 256>>>(1, n);                             // 4
    agg_kernel<<<nbAg, 256>>>(b1, 1, n);                          // 5
    gemm_kernel<<<nbGm, 256>>>(2, n);                             // 6
    agg3_kernel<<<nbAg, 256>>>(b2, Wf, n);                        // 7
    agg_final_kernel<<<nbN, 256>>>(bf, out, n);                   // 8
}